// round 16
// baseline (speedup 1.0000x reference)
#include <cuda_runtime.h>
#include <cuda_fp16.h>
#include <math.h>

#define Bb 64
#define Tt 2048
#define Vv 256
#define Uu 256
#define NEGV (-1e30f)

__device__ __half g_dh[(size_t)Bb * Tt * 256]; // d[b,t,i] fp16
__device__ float  g_Cpart[Bb * 256];           // per-8-row blank-logp partials
__device__ float  g_nll[Bb];
__device__ int    g_done;                      // zero-init; self-resetting

__device__ __forceinline__ void cp16(unsigned sa, const float* g) {
    asm volatile("cp.async.cg.shared.global [%0], [%1], 16;\n" :: "r"(sa), "l"(g) : "memory");
}
__device__ __forceinline__ void cp8(unsigned sa, const void* g) {
    asm volatile("cp.async.ca.shared.global [%0], [%1], 8;\n" :: "r"(sa), "l"(g) : "memory");
}
__device__ __forceinline__ void cpcommit() {
    asm volatile("cp.async.commit_group;\n" ::: "memory");
}
template<int N> __device__ __forceinline__ void cpwait() {
    asm volatile("cp.async.wait_group %0;\n" :: "n"(N) : "memory");
}
__device__ __forceinline__ void strel(unsigned a, int v) {
    asm volatile("st.release.cta.shared.b32 [%0], %1;" :: "r"(a), "r"(v) : "memory");
}
__device__ __forceinline__ int ldacq(unsigned a) {
    int v;
    asm volatile("ld.acquire.cta.shared.b32 %0, [%1];" : "=r"(v) : "r"(a) : "memory");
    return v;
}
__device__ __forceinline__ void spinw(unsigned a, int need) {
    if (ldacq(a) >= need) return;
    do { __nanosleep(32); } while (ldacq(a) < need);
}

// ---------------------------------------------------------------------------
// Kernel 1: fused lse + emission-delta gather (fp16 out) + blank-logp partials.
// (proven: 30.6us)
// ---------------------------------------------------------------------------
#define GB_ROWS 64
__global__ void __launch_bounds__(256) gather_kernel(const float* __restrict__ logits,
                                                     const int*  __restrict__ targets,
                                                     const int*  __restrict__ loglen) {
    __shared__ int   sTgt[Uu];
    __shared__ float sRow[8][4][Vv];

    const int b  = blockIdx.y;
    const int c  = blockIdx.x;
    const int L  = loglen[b];
    const int t0 = c * GB_ROWS;
    if (t0 >= L) return;

    const int tid = threadIdx.x, w = tid >> 5, lane = tid & 31;
    sTgt[tid] = targets[b * Uu + tid];
    __syncthreads();

    const int tbase = t0 + w * 8;
    if (tbase >= L) return;
    int nrows = L - tbase; if (nrows > 8) nrows = 8;

    const float* lg    = logits + ((size_t)b * Tt + tbase) * Vv;
    __half*      dOutH = g_dh   + ((size_t)b * Tt + tbase) * 256;

#pragma unroll
    for (int p = 0; p < 3; ++p) {
        if (p < nrows) {
            unsigned sa = (unsigned)__cvta_generic_to_shared(&sRow[w][p][lane * 8]);
            const float* g = lg + (size_t)p * Vv + lane * 8;
            cp16(sa, g);
            cp16(sa + 16, g + 4);
        }
        cpcommit();
    }

    float cb = 0.0f;
    for (int k = 0; k < nrows; ++k) {
        int pf = k + 3;
        if (pf < nrows) {
            unsigned sa = (unsigned)__cvta_generic_to_shared(&sRow[w][pf & 3][lane * 8]);
            const float* g = lg + (size_t)pf * Vv + lane * 8;
            cp16(sa, g);
            cp16(sa + 16, g + 4);
        }
        cpcommit();
        cpwait<3>();
        __syncwarp();

        const float* r = sRow[w][k & 3];
        float4 v0 = *(const float4*)&r[lane * 4];
        float4 v1 = *(const float4*)&r[128 + lane * 4];
        float s = __expf(v0.x) + __expf(v0.y) + __expf(v0.z) + __expf(v0.w)
                + __expf(v1.x) + __expf(v1.y) + __expf(v1.z) + __expf(v1.w);
#pragma unroll
        for (int o = 16; o; o >>= 1) s += __shfl_xor_sync(0xffffffffu, s, o);
        float lse = __logf(s);
        float r0  = __shfl_sync(0xffffffffu, v0.x, 0);
        cb += r0 - lse;

        int4 tg0 = *(const int4*)&sTgt[lane * 8];
        int4 tg1 = *(const int4*)&sTgt[lane * 8 + 4];
        __half2 a0 = __floats2half2_rn(r[tg0.x] - r0, r[tg0.y] - r0);
        __half2 a1 = __floats2half2_rn(r[tg0.z] - r0, r[tg0.w] - r0);
        __half2 a2 = __floats2half2_rn(r[tg1.x] - r0, r[tg1.y] - r0);
        __half2 a3 = __floats2half2_rn(r[tg1.z] - r0, r[tg1.w] - r0);
        uint4 pk;
        pk.x = *(unsigned*)&a0; pk.y = *(unsigned*)&a1;
        pk.z = *(unsigned*)&a2; pk.w = *(unsigned*)&a3;
        *(uint4*)&dOutH[(size_t)k * 256 + lane * 8] = pk;
        __syncwarp();
    }
    if (lane == 0) g_Cpart[b * 256 + (tbase >> 3)] = cb;
}

// ---------------------------------------------------------------------------
// Kernel 2: DIAGONAL-WAVEFRONT Viterbi DP. One block per batch, 2 warps:
//  wid 0 (lo):  pairs 0..127;  wid 1 (hi): pairs 128..255 + state 512.
// Lane k processes step t = i - 3k at warp-iteration i (skew 3). The boundary
// O3 crosses lanes via shfl with a 4-deep register FIFO -> SHFL latency is
// hidden under 4 step-times; the recurrence chain is the 12-cyc intra-lane
// FMNMX chain. Fill/drain phases use a gated (SEL) step variant.
// lo publishes per-32-iteration progress; hi lags ~3 superblocks.
// ---------------------------------------------------------------------------
#define LEAD 64
#define BNDN (Tt + 160)
__global__ void __launch_bounds__(64, 1) dp_kernel(const int* __restrict__ targets,
                                                   const int* __restrict__ loglen,
                                                   const int* __restrict__ tgtlen,
                                                   float* __restrict__ out) {
    extern __shared__ char sm[];
    // rings: [0,64K) wid0, [64K,128K) wid1 ; then bnd, sEO, dump, prog
    float* sBnd  = (float*)(sm + 131072);
    float* sEO   = sBnd + BNDN;            // sE[0..257] | sO at +258 (256)
    float* sDump = sEO + 520;
    int*   sProgP = (int*)(sDump + 32);

    const int tid  = threadIdx.x;
    const int wid  = tid >> 5;
    const int lane = tid & 31;
    const int b    = blockIdx.x;
    const int L    = loglen[b];
    const int Ut   = tgtlen[b];
    const unsigned uL = (unsigned)L;
    const int role = wid;
    const int pbase = role * 128 + lane * 4;
    const __half* __restrict__ emB = g_dh + (size_t)b * Tt * 256 + role * 128 + lane * 4;
    char* ringp = sm + wid * 65536;
    const unsigned ringB = (unsigned)__cvta_generic_to_shared(ringp);
    const unsigned lb    = (unsigned)lane * 8u;
    const unsigned bndB  = (unsigned)__cvta_generic_to_shared(sBnd);
    const unsigned progA = (unsigned)__cvta_generic_to_shared(sProgP);

    if (tid == 0) { *sProgP = 0; sBnd[0] = NEGV; }
    __syncthreads();

    float gate[4];
    {
        int prev = (pbase == 0) ? -1 : targets[b * Uu + pbase - 1];
#pragma unroll
        for (int j = 0; j < 4; ++j) {
            int cur = targets[b * Uu + pbase + j];
            gate[j] = (pbase + j >= 1 && cur != prev) ? 0.0f : NEGV;
            prev = cur;
        }
    }

    float E[4], O[4], fifo[4], bufv[4][4];
#pragma unroll
    for (int j = 0; j < 4; ++j) { E[j] = NEGV; O[j] = NEGV; fifo[j] = NEGV; }
    if (pbase == 0) E[0] = 0.0f;              // alpha_hat seed (lane0 role0)
    float Eex = NEGV;
    const float pOmask = (lane == 0) ? NEGV : 0.0f;   // role0 lane0
    const bool  lane0p = (lane == 0);
    const unsigned stBase = (lane == 31) ? bndB
                           : (unsigned)__cvta_generic_to_shared(&sDump[lane]);
    const unsigned stStep = (lane == 31) ? 4u : 0u;

    int tcur = -3 * lane - 1;                 // pre-incremented in step
    unsigned sbyte = (unsigned)(((2 - 3 * lane) & 255) << 8);

#define ISSUE4(I0)                                                            \
    {                                                                         \
        _Pragma("unroll")                                                     \
        for (int r_ = 0; r_ < 4; ++r_) {                                      \
            int row_ = (I0) + LEAD + r_;                                      \
            if (row_ > Tt - 1) row_ = Tt - 1;                                 \
            unsigned sa_ = ringB + (((unsigned)row_ & 255u) << 8) + lb;       \
            cp8(sa_, emB + (size_t)row_ * 256);                               \
        }                                                                     \
        cpcommit();                                                           \
    }

    // prologue cp.async: rows 0..63 (16 groups)
#pragma unroll
    for (int g2 = 0; g2 < 16; ++g2) ISSUE4(g2 * 4 - LEAD);
    cpwait<15>();                              // rows 0..3 resident (lane0 needs 0,1)

    // preload bufv[0], bufv[1] (rows i-3k for i=0,1; garbage for invalid lanes is fine)
#pragma unroll
    for (int p = 0; p < 2; ++p) {
        uint2 v_ = *(const uint2*)(ringp + (((p - 3 * lane) & 255) << 8) + lb);
        float2 fA_ = __half22float2(*(__half2*)&v_.x);
        float2 fB_ = __half22float2(*(__half2*)&v_.y);
        bufv[p][0] = fA_.x; bufv[p][1] = fA_.y; bufv[p][2] = fB_.x; bufv[p][3] = fB_.y;
    }

#define STEPBODY(PH, GATED, PO_EXPR, TAIL)                                    \
    {                                                                         \
        tcur++;                                                               \
        uint2 v_ = *(const uint2*)(ringp + sbyte + lb);                       \
        sbyte = (sbyte + 256u) & 65535u;                                      \
        float2 fA_ = __half22float2(*(__half2*)&v_.x);                        \
        float2 fB_ = __half22float2(*(__half2*)&v_.y);                        \
        bool val = true;                                                      \
        float pO = (PO_EXPR);                                                 \
        if (GATED) { val = ((unsigned)tcur < uL); pO = val ? pO : NEGV; }     \
        float o0=O[0],o1=O[1],o2=O[2],o3=O[3];                                \
        float e0=E[0],e1=E[1],e2=E[2],e3=E[3];                                \
        float O0n = fmaxf(fmaxf(o0,e0), pO + gate[0]) + bufv[PH][0];          \
        float O1n = fmaxf(fmaxf(o1,e1), o0 + gate[1]) + bufv[PH][1];          \
        float O2n = fmaxf(fmaxf(o2,e2), o1 + gate[2]) + bufv[PH][2];          \
        float O3n = fmaxf(fmaxf(o3,e3), o2 + gate[3]) + bufv[PH][3];          \
        float E0n = fmaxf(e0, pO), E1n = fmaxf(e1, o0);                       \
        float E2n = fmaxf(e2, o1), E3n = fmaxf(e3, o2);                       \
        if (GATED) {                                                          \
            O[0]=val?O0n:o0; O[1]=val?O1n:o1; O[2]=val?O2n:o2; O[3]=val?O3n:o3; \
            E[0]=val?E0n:e0; E[1]=val?E1n:e1; E[2]=val?E2n:e2; E[3]=val?E3n:e3; \
        } else {                                                              \
            O[0]=O0n; O[1]=O1n; O[2]=O2n; O[3]=O3n;                           \
            E[0]=E0n; E[1]=E1n; E[2]=E2n; E[3]=E3n;                           \
        }                                                                     \
        float ship = O[3];                                                    \
        float rec = __shfl_up_sync(0xffffffffu, ship, 1);                     \
        fifo[PH] = rec;                                                       \
        TAIL                                                                  \
        bufv[(PH+2)&3][0]=fA_.x; bufv[(PH+2)&3][1]=fA_.y;                     \
        bufv[(PH+2)&3][2]=fB_.x; bufv[(PH+2)&3][3]=fB_.y;                     \
    }

// role0 tail: store boundary (lane31 -> bnd[t+1], others -> dump)
#define TAIL0                                                                 \
        { int off_ = tcur + 1; if (off_ < 0) off_ = 0;                        \
          asm volatile("st.shared.b32 [%0], %1;"                              \
              :: "r"(stBase + (unsigned)off_ * stStep), "f"(ship)); }
// role1 tail: prefetch bnd, track Eex (GATED variant selects)
#define TAIL1(GATED)                                                          \
        { nb[(PH_CUR+2)&3] = sBnd[bidx]; bidx++;                              \
          float ex_ = fmaxf(Eex, o3);                                         \
          Eex = (GATED) ? (val ? ex_ : Eex) : ex_; }

    const int NSB    = (L + 124) >> 5;        // superblocks of 32 iterations
    const int sbGate = L >> 5;                // gated when sb<3 or sb>=sbGate

    if (role == 0) {
        for (int sb = 0; sb < NSB; ++sb) {
            const int base = sb << 5;
            if (sb >= 3 && sb < sbGate) {
                for (int m = 0; m < 8; ++m) {
                    const int i0 = base + (m << 2);
                    ISSUE4(i0); cpwait<15>();
                    STEPBODY(0, 0, fifo[0] + pOmask, TAIL0)
                    STEPBODY(1, 0, fifo[1] + pOmask, TAIL0)
                    STEPBODY(2, 0, fifo[2] + pOmask, TAIL0)
                    STEPBODY(3, 0, fifo[3] + pOmask, TAIL0)
                }
            } else {
                for (int m = 0; m < 8; ++m) {
                    const int i0 = base + (m << 2);
                    ISSUE4(i0); cpwait<15>();
                    STEPBODY(0, 1, fifo[0] + pOmask, TAIL0)
                    STEPBODY(1, 1, fifo[1] + pOmask, TAIL0)
                    STEPBODY(2, 1, fifo[2] + pOmask, TAIL0)
                    STEPBODY(3, 1, fifo[3] + pOmask, TAIL0)
                }
            }
            if (lane == 31 && sb >= 2) strel(progA, sb - 2);
        }
        cpwait<0>();
        if (lane == 31) strel(progA, 1 << 20);
    } else {
        float nb[4];
        int bidx = 2;
        spinw(progA, 1);                       // bnd[0..34] written
        __syncwarp();
        nb[0] = sBnd[0]; nb[1] = sBnd[1];
#define PO1(PH) (lane0p ? nb[PH] : fifo[PH])
        for (int sb = 0; sb < NSB; ++sb) {
            spinw(progA, sb + 1);
            __syncwarp();
            const int base = sb << 5;
            if (sb >= 3 && sb < sbGate) {
                for (int m = 0; m < 8; ++m) {
                    const int i0 = base + (m << 2);
                    ISSUE4(i0); cpwait<15>();
                    { const int PH_CUR = 0; STEPBODY(0, 0, PO1(0), TAIL1(0)) }
                    { const int PH_CUR = 1; STEPBODY(1, 0, PO1(1), TAIL1(0)) }
                    { const int PH_CUR = 2; STEPBODY(2, 0, PO1(2), TAIL1(0)) }
                    { const int PH_CUR = 3; STEPBODY(3, 0, PO1(3), TAIL1(0)) }
                }
            } else {
                for (int m = 0; m < 8; ++m) {
                    const int i0 = base + (m << 2);
                    ISSUE4(i0); cpwait<15>();
                    { const int PH_CUR = 0; STEPBODY(0, 1, PO1(0), TAIL1(1)) }
                    { const int PH_CUR = 1; STEPBODY(1, 1, PO1(1), TAIL1(1)) }
                    { const int PH_CUR = 2; STEPBODY(2, 1, PO1(2), TAIL1(1)) }
                    { const int PH_CUR = 3; STEPBODY(3, 1, PO1(3), TAIL1(1)) }
                }
            }
        }
        cpwait<0>();
#undef PO1
    }
#undef STEPBODY
#undef TAIL0
#undef TAIL1
#undef ISSUE4

    // blank-logp sum C_b (role 0, fixed order -> deterministic)
    float Cacc = 0.0f;
    if (role == 0) {
#pragma unroll
        for (int j = 0; j < 8; ++j) Cacc += g_Cpart[b * 256 + lane * 8 + j];
#pragma unroll
        for (int o2 = 16; o2; o2 >>= 1) Cacc += __shfl_xor_sync(0xffffffffu, Cacc, o2);
    }

    // epilogue: final states
    float* sE = sEO;
    float* sO = sEO + 258;
#pragma unroll
    for (int j = 0; j < 4; ++j) { sE[pbase + j] = E[j]; sO[pbase + j] = O[j]; }
    if (role == 1 && lane == 31) sE[256] = Eex;   // state 512 (E_256)
    __syncthreads();

    if (tid == 0) {
        float vb = sE[Ut];                        // alpha_hat[2*Ut]
        float vl = sO[Ut - 1];                    // alpha_hat[2*Ut - 1]
        g_nll[b] = -(fmaxf(vb, vl) + Cacc);
        __threadfence();
    }
    __syncthreads();
    if (wid == 0) {
        int last = 0;
        if (lane == 0) last = (atomicAdd(&g_done, 1) == Bb - 1) ? 1 : 0;
        last = __shfl_sync(0xffffffffu, last, 0);
        if (last) {
            __threadfence();
            float s = 0.0f, c = 0.0f;
            for (int bb = lane; bb < Bb; bb += 32) { s += g_nll[bb]; c += (float)loglen[bb]; }
#pragma unroll
            for (int o = 16; o; o >>= 1) {
                s += __shfl_xor_sync(0xffffffffu, s, o);
                c += __shfl_xor_sync(0xffffffffu, c, o);
            }
            if (lane == 0) { out[0] = s / c; g_done = 0; }
        }
    }
}

// ---------------------------------------------------------------------------
extern "C" void kernel_launch(void* const* d_in, const int* in_sizes, int n_in,
                              void* d_out, int out_size) {
    const float* logits  = (const float*)d_in[0];
    const int*   targets = (const int*)d_in[1];
    const int*   loglen  = (const int*)d_in[2];
    const int*   tgtlen  = (const int*)d_in[3];

    const int dpSmem = 131072 + (BNDN + 520 + 32 + 8) * (int)sizeof(float);   // ~142 KB
    cudaFuncSetAttribute(dp_kernel, cudaFuncAttributeMaxDynamicSharedMemorySize, dpSmem);

    gather_kernel<<<dim3(Tt / GB_ROWS, Bb), 256>>>(logits, targets, loglen);
    dp_kernel<<<Bb, 64, dpSmem>>>(targets, loglen, tgtlen, (float*)d_out);
}

// round 17
// speedup vs baseline: 1.0601x; 1.0601x over previous
#include <cuda_runtime.h>
#include <cuda_fp16.h>
#include <math.h>

#define Bb 64
#define Tt 2048
#define Vv 256
#define Uu 256
#define NEGV (-1e30f)

__device__ __half g_dh[(size_t)Bb * Tt * 256]; // d[b,t,i] fp16
__device__ float  g_Cpart[Bb * 256];           // per-8-row blank-logp partials
__device__ float  g_nll[Bb];
__device__ int    g_done;                      // zero-init; self-resetting

__device__ __forceinline__ void cp16(unsigned sa, const float* g) {
    asm volatile("cp.async.cg.shared.global [%0], [%1], 16;\n" :: "r"(sa), "l"(g) : "memory");
}
__device__ __forceinline__ void cp8(unsigned sa, const void* g) {
    asm volatile("cp.async.ca.shared.global [%0], [%1], 8;\n" :: "r"(sa), "l"(g) : "memory");
}
__device__ __forceinline__ void cpcommit() {
    asm volatile("cp.async.commit_group;\n" ::: "memory");
}
template<int N> __device__ __forceinline__ void cpwait() {
    asm volatile("cp.async.wait_group %0;\n" :: "n"(N) : "memory");
}
__device__ __forceinline__ void strel(unsigned a, int v) {
    asm volatile("st.release.cta.shared.b32 [%0], %1;" :: "r"(a), "r"(v) : "memory");
}
__device__ __forceinline__ int ldacq(unsigned a) {
    int v;
    asm volatile("ld.acquire.cta.shared.b32 %0, [%1];" : "=r"(v) : "r"(a) : "memory");
    return v;
}
__device__ __forceinline__ void spinw(unsigned a, int need) {
    if (ldacq(a) >= need) return;
    do { __nanosleep(32); } while (ldacq(a) < need);
}

// ---------------------------------------------------------------------------
// Kernel 1: fused lse + emission-delta gather (fp16 out) + blank-logp partials.
// (proven: 30.6us)
// ---------------------------------------------------------------------------
#define GB_ROWS 64
__global__ void __launch_bounds__(256) gather_kernel(const float* __restrict__ logits,
                                                     const int*  __restrict__ targets,
                                                     const int*  __restrict__ loglen) {
    __shared__ int   sTgt[Uu];
    __shared__ float sRow[8][4][Vv];

    const int b  = blockIdx.y;
    const int c  = blockIdx.x;
    const int L  = loglen[b];
    const int t0 = c * GB_ROWS;
    if (t0 >= L) return;

    const int tid = threadIdx.x, w = tid >> 5, lane = tid & 31;
    sTgt[tid] = targets[b * Uu + tid];
    __syncthreads();

    const int tbase = t0 + w * 8;
    if (tbase >= L) return;
    int nrows = L - tbase; if (nrows > 8) nrows = 8;

    const float* lg    = logits + ((size_t)b * Tt + tbase) * Vv;
    __half*      dOutH = g_dh   + ((size_t)b * Tt + tbase) * 256;

#pragma unroll
    for (int p = 0; p < 3; ++p) {
        if (p < nrows) {
            unsigned sa = (unsigned)__cvta_generic_to_shared(&sRow[w][p][lane * 8]);
            const float* g = lg + (size_t)p * Vv + lane * 8;
            cp16(sa, g);
            cp16(sa + 16, g + 4);
        }
        cpcommit();
    }

    float cb = 0.0f;
    for (int k = 0; k < nrows; ++k) {
        int pf = k + 3;
        if (pf < nrows) {
            unsigned sa = (unsigned)__cvta_generic_to_shared(&sRow[w][pf & 3][lane * 8]);
            const float* g = lg + (size_t)pf * Vv + lane * 8;
            cp16(sa, g);
            cp16(sa + 16, g + 4);
        }
        cpcommit();
        cpwait<3>();
        __syncwarp();

        const float* r = sRow[w][k & 3];
        float4 v0 = *(const float4*)&r[lane * 4];
        float4 v1 = *(const float4*)&r[128 + lane * 4];
        float s = __expf(v0.x) + __expf(v0.y) + __expf(v0.z) + __expf(v0.w)
                + __expf(v1.x) + __expf(v1.y) + __expf(v1.z) + __expf(v1.w);
#pragma unroll
        for (int o = 16; o; o >>= 1) s += __shfl_xor_sync(0xffffffffu, s, o);
        float lse = __logf(s);
        float r0  = __shfl_sync(0xffffffffu, v0.x, 0);
        cb += r0 - lse;

        int4 tg0 = *(const int4*)&sTgt[lane * 8];
        int4 tg1 = *(const int4*)&sTgt[lane * 8 + 4];
        __half2 a0 = __floats2half2_rn(r[tg0.x] - r0, r[tg0.y] - r0);
        __half2 a1 = __floats2half2_rn(r[tg0.z] - r0, r[tg0.w] - r0);
        __half2 a2 = __floats2half2_rn(r[tg1.x] - r0, r[tg1.y] - r0);
        __half2 a3 = __floats2half2_rn(r[tg1.z] - r0, r[tg1.w] - r0);
        uint4 pk;
        pk.x = *(unsigned*)&a0; pk.y = *(unsigned*)&a1;
        pk.z = *(unsigned*)&a2; pk.w = *(unsigned*)&a3;
        *(uint4*)&dOutH[(size_t)k * 256 + lane * 8] = pk;
        __syncwarp();
    }
    if (lane == 0) g_Cpart[b * 256 + (tbase >> 3)] = cb;
}

// ---------------------------------------------------------------------------
// Kernel 2: DIAGONAL-WAVEFRONT Viterbi DP (R16 semantics, slimmed step).
// One block per batch, 2 warps: wid0 = pairs 0..127, wid1 = pairs 128..255+512.
// Lane k runs step t = i - 3k at iteration i. Incremental addressing; bulk
// path has no tcur, no clamps, no SELs.
// ---------------------------------------------------------------------------
#define LEAD 64
#define BNDPAD 96
#define BNDN (Tt + 160)
__global__ void __launch_bounds__(64, 1) dp_kernel(const int* __restrict__ targets,
                                                   const int* __restrict__ loglen,
                                                   const int* __restrict__ tgtlen,
                                                   float* __restrict__ out) {
    extern __shared__ char sm[];
    float* sBndPad = (float*)(sm + 131072);       // [BNDPAD + BNDN]
    float* sBnd  = sBndPad + BNDPAD;
    float* sEO   = sBnd + BNDN;                   // sE[0..257] | sO at +258
    float* sDump = sEO + 520;
    int*   sProgP = (int*)(sDump + 32);

    const int tid  = threadIdx.x;
    const int wid  = tid >> 5;
    const int lane = tid & 31;
    const int b    = blockIdx.x;
    const int L    = loglen[b];
    const int Ut   = tgtlen[b];
    const unsigned uL = (unsigned)L;
    const int role = wid;
    const int pbase = role * 128 + lane * 4;
    const __half* __restrict__ emB = g_dh + (size_t)b * Tt * 256 + role * 128 + lane * 4;
    char* ringp = sm + wid * 65536;
    const unsigned ringB = (unsigned)__cvta_generic_to_shared(ringp);
    const unsigned lb    = (unsigned)lane * 8u;
    const char* rPtr = ringp + lb;
    const unsigned bndB  = (unsigned)__cvta_generic_to_shared(sBnd);
    const unsigned progA = (unsigned)__cvta_generic_to_shared(sProgP);

    if (tid == 0) { *sProgP = 0; sBnd[0] = NEGV; }
    __syncthreads();

    float gate[4];
    {
        int prev = (pbase == 0) ? -1 : targets[b * Uu + pbase - 1];
#pragma unroll
        for (int j = 0; j < 4; ++j) {
            int cur = targets[b * Uu + pbase + j];
            gate[j] = (pbase + j >= 1 && cur != prev) ? 0.0f : NEGV;
            prev = cur;
        }
    }

    float E[4], O[4], fifo[4], bufv[4][4];
#pragma unroll
    for (int j = 0; j < 4; ++j) { E[j] = NEGV; O[j] = NEGV; fifo[j] = NEGV; }
    if (pbase == 0) E[0] = 0.0f;              // alpha_hat seed (lane0 role0)
    float Eex = NEGV;
    const float pOmask = (lane == 0) ? NEGV : 0.0f;
    const bool  lane0p = (lane == 0);
    // boundary STS: lane31 -> bnd[tcur+1] (pad handles negatives), others -> dump
    const unsigned stStep = (lane == 31) ? 4u : 0u;
    unsigned stAddr = (lane == 31)
        ? (bndB - 368u)                        // first store lands at bnd[-92] (in pad)
        : (unsigned)__cvta_generic_to_shared(&sDump[lane]);

    int tcur = -3 * lane - 1;                 // maintained only in gated phases
    unsigned rOff = (unsigned)(((2 - 3 * lane) & 255) << 8);
    unsigned dOff = 16384u + lb;              // fast-issue dst (row 64)
    const __half* gPtr = emB + 64 * 256;      // fast-issue src (row 64)

#define ISSUE4F()                                                             \
    {                                                                         \
        unsigned b_ = ringB + dOff;                                           \
        cp8(b_,        gPtr);                                                 \
        cp8(b_ + 256u, gPtr + 256);                                           \
        cp8(b_ + 512u, gPtr + 512);                                           \
        cp8(b_ + 768u, gPtr + 768);                                           \
        dOff = (dOff + 1024u) & 65535u;                                       \
        gPtr += 1024;                                                         \
        cpcommit();                                                           \
    }
#define ISSUE4C(I0)                                                           \
    {                                                                         \
        _Pragma("unroll")                                                     \
        for (int r_ = 0; r_ < 4; ++r_) {                                      \
            int row_ = (I0) + LEAD + r_;                                      \
            if (row_ > Tt - 1) row_ = Tt - 1;                                 \
            cp8(ringB + (((unsigned)row_ & 255u) << 8) + lb,                  \
                emB + (size_t)row_ * 256);                                    \
        }                                                                     \
        cpcommit();                                                           \
    }
#define ISSUEANY(I0)                                                          \
    { if ((I0) <= Tt - LEAD - 4) { ISSUE4F(); } else { ISSUE4C(I0); } }

    // prologue: rows 0..63 (16 groups)
#pragma unroll
    for (int g2 = 0; g2 < 16; ++g2) {
#pragma unroll
        for (int r_ = 0; r_ < 4; ++r_) {
            int row_ = g2 * 4 + r_;
            cp8(ringB + ((unsigned)row_ << 8) + lb, emB + (size_t)row_ * 256);
        }
        cpcommit();
    }
    cpwait<15>();                              // rows 0..3 resident

#pragma unroll
    for (int p = 0; p < 2; ++p) {
        uint2 v_ = *(const uint2*)(rPtr + (((p - 3 * lane) & 255) << 8));
        float2 fA_ = __half22float2(*(__half2*)&v_.x);
        float2 fB_ = __half22float2(*(__half2*)&v_.y);
        bufv[p][0] = fA_.x; bufv[p][1] = fA_.y; bufv[p][2] = fB_.x; bufv[p][3] = fB_.y;
    }

// load + cvt + advance ring read, shared by all variants
#define LOADD()                                                               \
    uint2 v_ = *(const uint2*)(rPtr + rOff);                                  \
    rOff = (rOff + 256u) & 65535u;                                            \
    float2 fA_ = __half22float2(*(__half2*)&v_.x);                            \
    float2 fB_ = __half22float2(*(__half2*)&v_.y);
#define PUTB(PH)                                                              \
    bufv[(PH+2)&3][0]=fA_.x; bufv[(PH+2)&3][1]=fA_.y;                         \
    bufv[(PH+2)&3][2]=fB_.x; bufv[(PH+2)&3][3]=fB_.y;

// bulk role0
#define B0STEP(PH)                                                            \
    {                                                                         \
        LOADD()                                                               \
        float pO = fifo[PH] + pOmask;                                         \
        float o0=O[0],o1=O[1],o2=O[2],o3=O[3];                                \
        float e0=E[0],e1=E[1],e2=E[2],e3=E[3];                                \
        O[0]=fmaxf(fmaxf(o0,e0),pO+gate[0])+bufv[PH][0];                      \
        O[1]=fmaxf(fmaxf(o1,e1),o0+gate[1])+bufv[PH][1];                      \
        O[2]=fmaxf(fmaxf(o2,e2),o1+gate[2])+bufv[PH][2];                      \
        O[3]=fmaxf(fmaxf(o3,e3),o2+gate[3])+bufv[PH][3];                      \
        E[0]=fmaxf(e0,pO); E[1]=fmaxf(e1,o0);                                 \
        E[2]=fmaxf(e2,o1); E[3]=fmaxf(e3,o2);                                 \
        float ship = O[3];                                                    \
        fifo[PH] = __shfl_up_sync(0xffffffffu, ship, 1);                      \
        asm volatile("st.shared.b32 [%0], %1;" :: "r"(stAddr), "f"(ship));    \
        stAddr += stStep;                                                     \
        PUTB(PH)                                                              \
    }
// gated role0
#define G0STEP(PH)                                                            \
    {                                                                         \
        tcur++;                                                               \
        LOADD()                                                               \
        bool val = ((unsigned)tcur < uL);                                     \
        float pO = val ? (fifo[PH] + pOmask) : NEGV;                          \
        float o0=O[0],o1=O[1],o2=O[2],o3=O[3];                                \
        float e0=E[0],e1=E[1],e2=E[2],e3=E[3];                                \
        float O0n=fmaxf(fmaxf(o0,e0),pO+gate[0])+bufv[PH][0];                 \
        float O1n=fmaxf(fmaxf(o1,e1),o0+gate[1])+bufv[PH][1];                 \
        float O2n=fmaxf(fmaxf(o2,e2),o1+gate[2])+bufv[PH][2];                 \
        float O3n=fmaxf(fmaxf(o3,e3),o2+gate[3])+bufv[PH][3];                 \
        float E0n=fmaxf(e0,pO), E1n=fmaxf(e1,o0);                             \
        float E2n=fmaxf(e2,o1), E3n=fmaxf(e3,o2);                             \
        O[0]=val?O0n:o0; O[1]=val?O1n:o1; O[2]=val?O2n:o2; O[3]=val?O3n:o3;   \
        E[0]=val?E0n:e0; E[1]=val?E1n:e1; E[2]=val?E2n:e2; E[3]=val?E3n:e3;   \
        float ship = O[3];                                                    \
        fifo[PH] = __shfl_up_sync(0xffffffffu, ship, 1);                      \
        asm volatile("st.shared.b32 [%0], %1;" :: "r"(stAddr), "f"(ship));    \
        stAddr += stStep;                                                     \
        PUTB(PH)                                                              \
    }
// bulk role1
#define B1STEP(PH)                                                            \
    {                                                                         \
        LOADD()                                                               \
        float pO = lane0p ? nb[PH] : fifo[PH];                                \
        float o0=O[0],o1=O[1],o2=O[2],o3=O[3];                                \
        float e0=E[0],e1=E[1],e2=E[2],e3=E[3];                                \
        O[0]=fmaxf(fmaxf(o0,e0),pO+gate[0])+bufv[PH][0];                      \
        O[1]=fmaxf(fmaxf(o1,e1),o0+gate[1])+bufv[PH][1];                      \
        O[2]=fmaxf(fmaxf(o2,e2),o1+gate[2])+bufv[PH][2];                      \
        O[3]=fmaxf(fmaxf(o3,e3),o2+gate[3])+bufv[PH][3];                      \
        E[0]=fmaxf(e0,pO); E[1]=fmaxf(e1,o0);                                 \
        E[2]=fmaxf(e2,o1); E[3]=fmaxf(e3,o2);                                 \
        Eex = fmaxf(Eex, o3);                                                 \
        float ship = O[3];                                                    \
        fifo[PH] = __shfl_up_sync(0xffffffffu, ship, 1);                      \
        nb[(PH+2)&3] = *nbPtr; nbPtr++;                                       \
        PUTB(PH)                                                              \
    }
// gated role1
#define G1STEP(PH)                                                            \
    {                                                                         \
        tcur++;                                                               \
        LOADD()                                                               \
        bool val = ((unsigned)tcur < uL);                                     \
        float pOr = lane0p ? nb[PH] : fifo[PH];                               \
        float pO = val ? pOr : NEGV;                                          \
        float o0=O[0],o1=O[1],o2=O[2],o3=O[3];                                \
        float e0=E[0],e1=E[1],e2=E[2],e3=E[3];                                \
        float O0n=fmaxf(fmaxf(o0,e0),pO+gate[0])+bufv[PH][0];                 \
        float O1n=fmaxf(fmaxf(o1,e1),o0+gate[1])+bufv[PH][1];                 \
        float O2n=fmaxf(fmaxf(o2,e2),o1+gate[2])+bufv[PH][2];                 \
        float O3n=fmaxf(fmaxf(o3,e3),o2+gate[3])+bufv[PH][3];                 \
        float E0n=fmaxf(e0,pO), E1n=fmaxf(e1,o0);                             \
        float E2n=fmaxf(e2,o1), E3n=fmaxf(e3,o2);                             \
        O[0]=val?O0n:o0; O[1]=val?O1n:o1; O[2]=val?O2n:o2; O[3]=val?O3n:o3;   \
        E[0]=val?E0n:e0; E[1]=val?E1n:e1; E[2]=val?E2n:e2; E[3]=val?E3n:e3;   \
        float ex_ = fmaxf(Eex, o3);                                           \
        Eex = val ? ex_ : Eex;                                                \
        float ship = O[3];                                                    \
        fifo[PH] = __shfl_up_sync(0xffffffffu, ship, 1);                      \
        nb[(PH+2)&3] = *nbPtr; nbPtr++;                                       \
        PUTB(PH)                                                              \
    }

    const int NSB    = (L + 124) >> 5;
    const int sbGate = L >> 5;

    if (role == 0) {
        // fill: sb 0..2 (gated)
        for (int sb = 0; sb < 3; ++sb) {
            const int base = sb << 5;
            for (int m = 0; m < 8; ++m) {
                const int i0 = base + (m << 2);
                ISSUEANY(i0); cpwait<15>();
                G0STEP(0) G0STEP(1) G0STEP(2) G0STEP(3)
            }
            if (lane == 31 && sb >= 2) strel(progA, sb - 2);
        }
        // bulk: sb 3..sbGate-1
        for (int sb = 3; sb < sbGate; ++sb) {
            const int base = sb << 5;
            for (int m = 0; m < 8; ++m) {
                const int i0 = base + (m << 2);
                ISSUEANY(i0); cpwait<15>();
                B0STEP(0) B0STEP(1) B0STEP(2) B0STEP(3)
            }
            if (lane == 31) strel(progA, sb - 2);
        }
        // drain: sb sbGate..NSB-1 (gated); resync tcur
        tcur = (sbGate << 5) - 3 * lane - 1;
        for (int sb = sbGate; sb < NSB; ++sb) {
            const int base = sb << 5;
            for (int m = 0; m < 8; ++m) {
                const int i0 = base + (m << 2);
                ISSUEANY(i0); cpwait<15>();
                G0STEP(0) G0STEP(1) G0STEP(2) G0STEP(3)
            }
            if (lane == 31) strel(progA, sb - 2);
        }
        cpwait<0>();
        if (lane == 31) strel(progA, 1 << 20);
    } else {
        float nb[4];
        spinw(progA, 1);
        __syncwarp();
        nb[0] = sBnd[0]; nb[1] = sBnd[1];
        const float* nbPtr = sBnd + 2;
        // fill: sb 0..2 (gated)
        for (int sb = 0; sb < 3; ++sb) {
            spinw(progA, sb + 1);
            __syncwarp();
            const int base = sb << 5;
            for (int m = 0; m < 8; ++m) {
                const int i0 = base + (m << 2);
                ISSUEANY(i0); cpwait<15>();
                G1STEP(0) G1STEP(1) G1STEP(2) G1STEP(3)
            }
        }
        // bulk
        for (int sb = 3; sb < sbGate; ++sb) {
            spinw(progA, sb + 1);
            __syncwarp();
            const int base = sb << 5;
            for (int m = 0; m < 8; ++m) {
                const int i0 = base + (m << 2);
                ISSUEANY(i0); cpwait<15>();
                B1STEP(0) B1STEP(1) B1STEP(2) B1STEP(3)
            }
        }
        // drain
        tcur = (sbGate << 5) - 3 * lane - 1;
        for (int sb = sbGate; sb < NSB; ++sb) {
            spinw(progA, sb + 1);
            __syncwarp();
            const int base = sb << 5;
            for (int m = 0; m < 8; ++m) {
                const int i0 = base + (m << 2);
                ISSUEANY(i0); cpwait<15>();
                G1STEP(0) G1STEP(1) G1STEP(2) G1STEP(3)
            }
        }
        cpwait<0>();
    }
#undef B0STEP
#undef G0STEP
#undef B1STEP
#undef G1STEP
#undef LOADD
#undef PUTB
#undef ISSUE4F
#undef ISSUE4C
#undef ISSUEANY

    // blank-logp sum C_b (role 0, fixed order -> deterministic)
    float Cacc = 0.0f;
    if (role == 0) {
#pragma unroll
        for (int j = 0; j < 8; ++j) Cacc += g_Cpart[b * 256 + lane * 8 + j];
#pragma unroll
        for (int o2 = 16; o2; o2 >>= 1) Cacc += __shfl_xor_sync(0xffffffffu, Cacc, o2);
    }

    // epilogue: final states
    float* sE = sEO;
    float* sO = sEO + 258;
#pragma unroll
    for (int j = 0; j < 4; ++j) { sE[pbase + j] = E[j]; sO[pbase + j] = O[j]; }
    if (role == 1 && lane == 31) sE[256] = Eex;   // state 512 (E_256)
    __syncthreads();

    if (tid == 0) {
        float vb = sE[Ut];                        // alpha_hat[2*Ut]
        float vl = sO[Ut - 1];                    // alpha_hat[2*Ut - 1]
        g_nll[b] = -(fmaxf(vb, vl) + Cacc);
        __threadfence();
    }
    __syncthreads();
    if (wid == 0) {
        int last = 0;
        if (lane == 0) last = (atomicAdd(&g_done, 1) == Bb - 1) ? 1 : 0;
        last = __shfl_sync(0xffffffffu, last, 0);
        if (last) {
            __threadfence();
            float s = 0.0f, c = 0.0f;
            for (int bb = lane; bb < Bb; bb += 32) { s += g_nll[bb]; c += (float)loglen[bb]; }
#pragma unroll
            for (int o = 16; o; o >>= 1) {
                s += __shfl_xor_sync(0xffffffffu, s, o);
                c += __shfl_xor_sync(0xffffffffu, c, o);
            }
            if (lane == 0) { out[0] = s / c; g_done = 0; }
        }
    }
}

// ---------------------------------------------------------------------------
extern "C" void kernel_launch(void* const* d_in, const int* in_sizes, int n_in,
                              void* d_out, int out_size) {
    const float* logits  = (const float*)d_in[0];
    const int*   targets = (const int*)d_in[1];
    const int*   loglen  = (const int*)d_in[2];
    const int*   tgtlen  = (const int*)d_in[3];

    const int dpSmem = 131072 + (BNDPAD + BNDN + 520 + 32 + 8) * (int)sizeof(float);
    cudaFuncSetAttribute(dp_kernel, cudaFuncAttributeMaxDynamicSharedMemorySize, dpSmem);

    gather_kernel<<<dim3(Tt / GB_ROWS, Bb), 256>>>(logits, targets, loglen);
    dp_kernel<<<Bb, 64, dpSmem>>>(targets, loglen, tgtlen, (float*)d_out);
}